// round 1
// baseline (speedup 1.0000x reference)
#include <cuda_runtime.h>
#include <cuda_fp16.h>

#define NTOK      64
#define DIMC      128
#define NHEADS    4
#define HDIM      32
#define NWIN      256
#define NWINDOWS  8192
#define ATT_SCALE 0.17677669529663687f

// ---------------- device scratch (allowed: __device__ globals) ----------------
__device__ __half g_wqkv[3 * DIMC * DIMC];           // [384][128] fp16
__device__ __half g_wproj[DIMC * DIMC];              // [128][128] fp16
__device__ float  g_bm[NWIN * NHEADS * NTOK * NTOK]; // [w][h][n][m] bias+mask

// ---------------- prep kernels ----------------
__global__ void prep_weights_k(const float* __restrict__ qkv_w,
                               const float* __restrict__ proj_w) {
    int i = blockIdx.x * blockDim.x + threadIdx.x;
    if (i < 3 * DIMC * DIMC) g_wqkv[i] = __float2half_rn(qkv_w[i]);
    if (i < DIMC * DIMC)     g_wproj[i] = __float2half_rn(proj_w[i]);
}

__global__ void prep_bm_k(const float* __restrict__ mask,
                          const float* __restrict__ bias_table,
                          const int* __restrict__ rel_index) {
    int e = blockIdx.x * blockDim.x + threadIdx.x;   // linear over [w][h][n][m]
    int m = e & 63, n = (e >> 6) & 63, h = (e >> 12) & 3, w = e >> 14;
    g_bm[e] = mask[(w * 64 + n) * 64 + m]
            + bias_table[rel_index[n * 64 + m] * NHEADS + h];
}

// ---------------- helpers ----------------
__device__ __forceinline__ unsigned lds_u32(const __half* p) {
    return *reinterpret_cast<const unsigned*>(p);
}
__device__ __forceinline__ unsigned h2u(__half2 v) {
    return *reinterpret_cast<unsigned*>(&v);
}
__device__ __forceinline__ void mma_16816(float c[4], const unsigned a[4],
                                          const unsigned b[2]) {
    asm volatile(
        "mma.sync.aligned.m16n8k16.row.col.f32.f16.f16.f32 "
        "{%0,%1,%2,%3}, {%4,%5,%6,%7}, {%8,%9}, {%0,%1,%2,%3};\n"
        : "+f"(c[0]), "+f"(c[1]), "+f"(c[2]), "+f"(c[3])
        : "r"(a[0]), "r"(a[1]), "r"(a[2]), "r"(a[3]), "r"(b[0]), "r"(b[1]));
}

// SMEM byte offsets (flat dynamic smem, manually overlaid by phase)
#define SM_QH 0        // [64][136] half = 17408
#define SM_KH 17408    // [64][136] half
#define SM_VT 34816    // [128][72] half (v transposed: vt[d][m]) = 18432
#define SM_OH 53248    // [64][136] half
#define SM_XH 70656    // [64][136] half
#define SM_WS 88064    // weight staging, up to 256x[40] half = 20480
#define SMEM_BYTES 108544

// ---------------- main fused kernel: 1 window per CTA ----------------
__global__ void __launch_bounds__(256, 2)
swin_attn_kernel(const float* __restrict__ x,
                 const float* __restrict__ qkv_b,
                 const float* __restrict__ proj_b,
                 float* __restrict__ out) {
    extern __shared__ char smem[];
    __half* qh = (__half*)(smem + SM_QH);
    __half* kh = (__half*)(smem + SM_KH);
    __half* vt = (__half*)(smem + SM_VT);
    __half* oh = (__half*)(smem + SM_OH);
    __half* xh = (__half*)(smem + SM_XH);
    __half* ws = (__half*)(smem + SM_WS);

    const int tid  = threadIdx.x;
    const int lane = tid & 31;
    const int warp = tid >> 5;
    const int l4   = lane >> 2;   // fragment row group
    const int lm   = lane & 3;    // fragment col/k group
    const int b    = blockIdx.x;

    // ---------- phase 0: x tile -> fp16 smem ----------
    {
        const float4* xg = (const float4*)(x + (size_t)b * NTOK * DIMC);
#pragma unroll
        for (int i = 0; i < 8; ++i) {
            int idx = tid + i * 256;          // 2048 float4 total
            float4 v = xg[idx];
            int row = idx >> 5;               // 32 float4 per 128-wide row
            int col = (idx & 31) << 2;
            __half2* dst = (__half2*)(xh + row * 136 + col);
            dst[0] = __floats2half2_rn(v.x, v.y);
            dst[1] = __floats2half2_rn(v.z, v.w);
        }
    }
    __syncthreads();

    const int mi = warp & 1;   // M-half (rows mi*32..+31)
    const int ni = warp >> 1;  // N-quarter

    // ---------- phase 1 pass A: q,k = X @ Wqkv[0:256]^T ----------
    {
        float c[2][8][4];
#pragma unroll
        for (int a = 0; a < 2; ++a)
#pragma unroll
            for (int t = 0; t < 8; ++t)
#pragma unroll
                for (int r = 0; r < 4; ++r) c[a][t][r] = 0.f;

        for (int kb = 0; kb < 4; ++kb) {
            // stage Wqkv rows 0..255, k-chunk kb*32..+31 (pad rows to 40 halves)
#pragma unroll
            for (int i = 0; i < 8; ++i) {
                int idx = tid + i * 256;          // 2048 uint2
                int r = idx >> 3;
                int kk = (idx & 7) << 2;
                *(uint2*)(ws + r * 40 + kk) =
                    *(const uint2*)(g_wqkv + r * 128 + kb * 32 + kk);
            }
            __syncthreads();
#pragma unroll
            for (int kt = 0; kt < 2; ++kt) {
                int kc = kb * 32 + kt * 16;
                unsigned a[2][4];
#pragma unroll
                for (int mt = 0; mt < 2; ++mt) {
                    int r0 = mi * 32 + mt * 16 + l4;
                    a[mt][0] = lds_u32(xh + r0 * 136 + kc + lm * 2);
                    a[mt][1] = lds_u32(xh + (r0 + 8) * 136 + kc + lm * 2);
                    a[mt][2] = lds_u32(xh + r0 * 136 + kc + 8 + lm * 2);
                    a[mt][3] = lds_u32(xh + (r0 + 8) * 136 + kc + 8 + lm * 2);
                }
#pragma unroll
                for (int nt = 0; nt < 8; ++nt) {
                    int jr = ni * 64 + nt * 8 + l4;
                    unsigned bb[2];
                    bb[0] = lds_u32(ws + jr * 40 + kt * 16 + lm * 2);
                    bb[1] = lds_u32(ws + jr * 40 + kt * 16 + 8 + lm * 2);
                    mma_16816(c[0][nt], a[0], bb);
                    mma_16816(c[1][nt], a[1], bb);
                }
            }
            __syncthreads();
        }
        // epilogue: + qkv_b, -> qh / kh fp16
#pragma unroll
        for (int mt = 0; mt < 2; ++mt)
#pragma unroll
            for (int nt = 0; nt < 8; ++nt) {
                int col = ni * 64 + nt * 8 + lm * 2;
                int r0 = mi * 32 + mt * 16 + l4;
                float2 bv = *(const float2*)(qkv_b + col);
                __half2 h0 = __floats2half2_rn(c[mt][nt][0] + bv.x, c[mt][nt][1] + bv.y);
                __half2 h1 = __floats2half2_rn(c[mt][nt][2] + bv.x, c[mt][nt][3] + bv.y);
                __half* base = (col < 128) ? qh : kh;
                int cc = col & 127;
                *(__half2*)(base + r0 * 136 + cc) = h0;
                *(__half2*)(base + (r0 + 8) * 136 + cc) = h1;
            }
    }

    // ---------- phase 1 pass B: v = X @ Wqkv[256:384]^T, stored transposed ----------
    {
        float c[2][4][4];
#pragma unroll
        for (int a = 0; a < 2; ++a)
#pragma unroll
            for (int t = 0; t < 4; ++t)
#pragma unroll
                for (int r = 0; r < 4; ++r) c[a][t][r] = 0.f;

        for (int kb = 0; kb < 4; ++kb) {
#pragma unroll
            for (int i = 0; i < 4; ++i) {
                int idx = tid + i * 256;          // 1024 uint2 (128 rows x 32)
                int r = idx >> 3;
                int kk = (idx & 7) << 2;
                *(uint2*)(ws + r * 40 + kk) =
                    *(const uint2*)(g_wqkv + (256 + r) * 128 + kb * 32 + kk);
            }
            __syncthreads();
#pragma unroll
            for (int kt = 0; kt < 2; ++kt) {
                int kc = kb * 32 + kt * 16;
                unsigned a[2][4];
#pragma unroll
                for (int mt = 0; mt < 2; ++mt) {
                    int r0 = mi * 32 + mt * 16 + l4;
                    a[mt][0] = lds_u32(xh + r0 * 136 + kc + lm * 2);
                    a[mt][1] = lds_u32(xh + (r0 + 8) * 136 + kc + lm * 2);
                    a[mt][2] = lds_u32(xh + r0 * 136 + kc + 8 + lm * 2);
                    a[mt][3] = lds_u32(xh + (r0 + 8) * 136 + kc + 8 + lm * 2);
                }
#pragma unroll
                for (int nt = 0; nt < 4; ++nt) {
                    int jr = ni * 32 + nt * 8 + l4;
                    unsigned bb[2];
                    bb[0] = lds_u32(ws + jr * 40 + kt * 16 + lm * 2);
                    bb[1] = lds_u32(ws + jr * 40 + kt * 16 + 8 + lm * 2);
                    mma_16816(c[0][nt], a[0], bb);
                    mma_16816(c[1][nt], a[1], bb);
                }
            }
            __syncthreads();
        }
        // epilogue: + bias, write v^T: vt[d][m]
#pragma unroll
        for (int mt = 0; mt < 2; ++mt)
#pragma unroll
            for (int nt = 0; nt < 4; ++nt) {
                int col = 256 + ni * 32 + nt * 8 + lm * 2;
                int d = col - 256;
                int r0 = mi * 32 + mt * 16 + l4;
                float2 bv = *(const float2*)(qkv_b + col);
                vt[d * 72 + r0]           = __float2half_rn(c[mt][nt][0] + bv.x);
                vt[(d + 1) * 72 + r0]     = __float2half_rn(c[mt][nt][1] + bv.y);
                vt[d * 72 + r0 + 8]       = __float2half_rn(c[mt][nt][2] + bv.x);
                vt[(d + 1) * 72 + r0 + 8] = __float2half_rn(c[mt][nt][3] + bv.y);
            }
    }
    __syncthreads();

    // ---------- phase 2: attention (2 warps per head) ----------
    {
        const int h = warp >> 1;
        const int mh = warp & 1;
        const int rowbase = mh * 32;

        float s[2][8][4];
#pragma unroll
        for (int a = 0; a < 2; ++a)
#pragma unroll
            for (int t = 0; t < 8; ++t)
#pragma unroll
                for (int r = 0; r < 4; ++r) s[a][t][r] = 0.f;

        // S = Q @ K^T
#pragma unroll
        for (int kt = 0; kt < 2; ++kt) {
            int kc = h * 32 + kt * 16;
            unsigned a[2][4];
#pragma unroll
            for (int mt = 0; mt < 2; ++mt) {
                int r0 = rowbase + mt * 16 + l4;
                a[mt][0] = lds_u32(qh + r0 * 136 + kc + lm * 2);
                a[mt][1] = lds_u32(qh + (r0 + 8) * 136 + kc + lm * 2);
                a[mt][2] = lds_u32(qh + r0 * 136 + kc + 8 + lm * 2);
                a[mt][3] = lds_u32(qh + (r0 + 8) * 136 + kc + 8 + lm * 2);
            }
#pragma unroll
            for (int nt = 0; nt < 8; ++nt) {
                int mcol = nt * 8 + l4;
                unsigned bb[2];
                bb[0] = lds_u32(kh + mcol * 136 + kc + lm * 2);
                bb[1] = lds_u32(kh + mcol * 136 + kc + 8 + lm * 2);
                mma_16816(s[0][nt], a[0], bb);
                mma_16816(s[1][nt], a[1], bb);
            }
        }

        // scale + bias+mask, softmax (rows live in 4-lane groups)
        const float* bm = g_bm + ((size_t)((b & 255) * 4 + h)) * 64 * 64;
        float rmax[4] = {-1e30f, -1e30f, -1e30f, -1e30f};
#pragma unroll
        for (int mt = 0; mt < 2; ++mt) {
            int r0 = rowbase + mt * 16 + l4;
#pragma unroll
            for (int nt = 0; nt < 8; ++nt) {
                int col = nt * 8 + lm * 2;
                float2 b0 = *(const float2*)(bm + r0 * 64 + col);
                float2 b1 = *(const float2*)(bm + (r0 + 8) * 64 + col);
                s[mt][nt][0] = s[mt][nt][0] * ATT_SCALE + b0.x;
                s[mt][nt][1] = s[mt][nt][1] * ATT_SCALE + b0.y;
                s[mt][nt][2] = s[mt][nt][2] * ATT_SCALE + b1.x;
                s[mt][nt][3] = s[mt][nt][3] * ATT_SCALE + b1.y;
                rmax[mt * 2]     = fmaxf(rmax[mt * 2],     fmaxf(s[mt][nt][0], s[mt][nt][1]));
                rmax[mt * 2 + 1] = fmaxf(rmax[mt * 2 + 1], fmaxf(s[mt][nt][2], s[mt][nt][3]));
            }
        }
#pragma unroll
        for (int i = 0; i < 4; ++i) {
            rmax[i] = fmaxf(rmax[i], __shfl_xor_sync(0xffffffffu, rmax[i], 1));
            rmax[i] = fmaxf(rmax[i], __shfl_xor_sync(0xffffffffu, rmax[i], 2));
        }
        float rsum[4] = {0.f, 0.f, 0.f, 0.f};
#pragma unroll
        for (int mt = 0; mt < 2; ++mt)
#pragma unroll
            for (int nt = 0; nt < 8; ++nt) {
                s[mt][nt][0] = __expf(s[mt][nt][0] - rmax[mt * 2]);
                s[mt][nt][1] = __expf(s[mt][nt][1] - rmax[mt * 2]);
                s[mt][nt][2] = __expf(s[mt][nt][2] - rmax[mt * 2 + 1]);
                s[mt][nt][3] = __expf(s[mt][nt][3] - rmax[mt * 2 + 1]);
                rsum[mt * 2]     += s[mt][nt][0] + s[mt][nt][1];
                rsum[mt * 2 + 1] += s[mt][nt][2] + s[mt][nt][3];
            }
#pragma unroll
        for (int i = 0; i < 4; ++i) {
            rsum[i] += __shfl_xor_sync(0xffffffffu, rsum[i], 1);
            rsum[i] += __shfl_xor_sync(0xffffffffu, rsum[i], 2);
        }
        float rinv[4];
#pragma unroll
        for (int i = 0; i < 4; ++i) rinv[i] = 1.0f / rsum[i];

        // repack normalized P into A fragments (S C-frag layout == A-frag layout)
        unsigned pa[2][4][4];
#pragma unroll
        for (int mt = 0; mt < 2; ++mt)
#pragma unroll
            for (int k2 = 0; k2 < 4; ++k2) {
                pa[mt][k2][0] = h2u(__floats2half2_rn(s[mt][2 * k2][0] * rinv[2 * mt],
                                                      s[mt][2 * k2][1] * rinv[2 * mt]));
                pa[mt][k2][1] = h2u(__floats2half2_rn(s[mt][2 * k2][2] * rinv[2 * mt + 1],
                                                      s[mt][2 * k2][3] * rinv[2 * mt + 1]));
                pa[mt][k2][2] = h2u(__floats2half2_rn(s[mt][2 * k2 + 1][0] * rinv[2 * mt],
                                                      s[mt][2 * k2 + 1][1] * rinv[2 * mt]));
                pa[mt][k2][3] = h2u(__floats2half2_rn(s[mt][2 * k2 + 1][2] * rinv[2 * mt + 1],
                                                      s[mt][2 * k2 + 1][3] * rinv[2 * mt + 1]));
            }

        // O = P @ V
        float o[2][4][4];
#pragma unroll
        for (int a = 0; a < 2; ++a)
#pragma unroll
            for (int t = 0; t < 4; ++t)
#pragma unroll
                for (int r = 0; r < 4; ++r) o[a][t][r] = 0.f;
#pragma unroll
        for (int k2 = 0; k2 < 4; ++k2)
#pragma unroll
            for (int nt = 0; nt < 4; ++nt) {
                int dd = nt * 8 + l4;
                unsigned bb[2];
                bb[0] = lds_u32(vt + (h * 32 + dd) * 72 + k2 * 16 + lm * 2);
                bb[1] = lds_u32(vt + (h * 32 + dd) * 72 + k2 * 16 + 8 + lm * 2);
                mma_16816(o[0][nt], pa[0][k2], bb);
                mma_16816(o[1][nt], pa[1][k2], bb);
            }
        // write O (fp16) into oh
#pragma unroll
        for (int mt = 0; mt < 2; ++mt)
#pragma unroll
            for (int nt = 0; nt < 4; ++nt) {
                int col = h * 32 + nt * 8 + lm * 2;
                int r0 = rowbase + mt * 16 + l4;
                *(__half2*)(oh + r0 * 136 + col) =
                    __floats2half2_rn(o[mt][nt][0], o[mt][nt][1]);
                *(__half2*)(oh + (r0 + 8) * 136 + col) =
                    __floats2half2_rn(o[mt][nt][2], o[mt][nt][3]);
            }
    }
    __syncthreads();

    // ---------- phase 3: out = O @ Wproj^T + proj_b ----------
    {
        float c[2][4][4];
#pragma unroll
        for (int a = 0; a < 2; ++a)
#pragma unroll
            for (int t = 0; t < 4; ++t)
#pragma unroll
                for (int r = 0; r < 4; ++r) c[a][t][r] = 0.f;

        for (int kb = 0; kb < 4; ++kb) {
#pragma unroll
            for (int i = 0; i < 4; ++i) {
                int idx = tid + i * 256;          // 1024 uint2
                int r = idx >> 3;
                int kk = (idx & 7) << 2;
                *(uint2*)(ws + r * 40 + kk) =
                    *(const uint2*)(g_wproj + r * 128 + kb * 32 + kk);
            }
            __syncthreads();
#pragma unroll
            for (int kt = 0; kt < 2; ++kt) {
                int kc = kb * 32 + kt * 16;
                unsigned a[2][4];
#pragma unroll
                for (int mt = 0; mt < 2; ++mt) {
                    int r0 = mi * 32 + mt * 16 + l4;
                    a[mt][0] = lds_u32(oh + r0 * 136 + kc + lm * 2);
                    a[mt][1] = lds_u32(oh + (r0 + 8) * 136 + kc + lm * 2);
                    a[mt][2] = lds_u32(oh + r0 * 136 + kc + 8 + lm * 2);
                    a[mt][3] = lds_u32(oh + (r0 + 8) * 136 + kc + 8 + lm * 2);
                }
#pragma unroll
                for (int nt = 0; nt < 4; ++nt) {
                    int jr = ni * 32 + nt * 8 + l4;
                    unsigned bb[2];
                    bb[0] = lds_u32(ws + jr * 40 + kt * 16 + lm * 2);
                    bb[1] = lds_u32(ws + jr * 40 + kt * 16 + 8 + lm * 2);
                    mma_16816(c[0][nt], a[0], bb);
                    mma_16816(c[1][nt], a[1], bb);
                }
            }
            __syncthreads();
        }
        // epilogue: + proj_b, store fp32
        float* og = out + (size_t)b * NTOK * DIMC;
#pragma unroll
        for (int mt = 0; mt < 2; ++mt)
#pragma unroll
            for (int nt = 0; nt < 4; ++nt) {
                int col = ni * 32 + nt * 8 + lm * 2;
                int r0 = mi * 32 + mt * 16 + l4;
                float2 pb = *(const float2*)(proj_b + col);
                float2 v0 = {c[mt][nt][0] + pb.x, c[mt][nt][1] + pb.y};
                float2 v1 = {c[mt][nt][2] + pb.x, c[mt][nt][3] + pb.y};
                *(float2*)(og + r0 * 128 + col) = v0;
                *(float2*)(og + (r0 + 8) * 128 + col) = v1;
            }
    }
}

// ---------------- launch ----------------
extern "C" void kernel_launch(void* const* d_in, const int* in_sizes, int n_in,
                              void* d_out, int out_size) {
    const float* x       = (const float*)d_in[0];
    const float* mask    = (const float*)d_in[1];
    const float* qkv_w   = (const float*)d_in[2];
    const float* qkv_b   = (const float*)d_in[3];
    const float* proj_w  = (const float*)d_in[4];
    const float* proj_b  = (const float*)d_in[5];
    const float* bias_t  = (const float*)d_in[6];
    const int*   rel_idx = (const int*)d_in[7];
    float* out = (float*)d_out;

    prep_weights_k<<<(3 * DIMC * DIMC + 255) / 256, 256>>>(qkv_w, proj_w);
    prep_bm_k<<<(NWIN * NHEADS * NTOK * NTOK) / 256, 256>>>(mask, bias_t, rel_idx);

    cudaFuncSetAttribute(swin_attn_kernel,
                         cudaFuncAttributeMaxDynamicSharedMemorySize, SMEM_BYTES);
    swin_attn_kernel<<<NWINDOWS, 256, SMEM_BYTES>>>(x, qkv_b, proj_b, out);
}

// round 3
// speedup vs baseline: 1.1921x; 1.1921x over previous
#include <cuda_runtime.h>
#include <cuda_fp16.h>

#define NTOK      64
#define DIMC      128
#define NHEADS    4
#define NWIN      256
#define NWINDOWS  8192
#define ATT_SCALE 0.17677669529663687f

// ---------------- device scratch ----------------
__device__ __half g_wqkv[3 * DIMC * DIMC];           // [384][128] fp16
__device__ __half g_wproj[DIMC * DIMC];              // [128][128] fp16
__device__ float  g_bm[NWIN * NHEADS * NTOK * NTOK]; // [w][h][n][m] bias+mask

// ---------------- merged prep kernel ----------------
__global__ void prep_all_k(const float* __restrict__ mask,
                           const float* __restrict__ bias_table,
                           const int* __restrict__ rel_index,
                           const float* __restrict__ qkv_w,
                           const float* __restrict__ proj_w) {
    int e = blockIdx.x * blockDim.x + threadIdx.x;
    if (e < 3 * DIMC * DIMC) g_wqkv[e] = __float2half_rn(qkv_w[e]);
    if (e < DIMC * DIMC)     g_wproj[e] = __float2half_rn(proj_w[e]);
    int m = e & 63, n = (e >> 6) & 63, h = (e >> 12) & 3, w = e >> 14;
    g_bm[e] = mask[(w * 64 + n) * 64 + m]
            + bias_table[rel_index[n * 64 + m] * NHEADS + h];
}

// ---------------- helpers ----------------
__device__ __forceinline__ unsigned lds_u32(const __half* p) {
    return *reinterpret_cast<const unsigned*>(p);
}
__device__ __forceinline__ unsigned h2u(__half2 v) {
    return *reinterpret_cast<unsigned*>(&v);
}
__device__ __forceinline__ void mma_16816(float c[4], const unsigned a[4],
                                          const unsigned b[2]) {
    asm volatile(
        "mma.sync.aligned.m16n8k16.row.col.f32.f16.f16.f32 "
        "{%0,%1,%2,%3}, {%4,%5,%6,%7}, {%8,%9}, {%0,%1,%2,%3};\n"
        : "+f"(c[0]), "+f"(c[1]), "+f"(c[2]), "+f"(c[3])
        : "r"(a[0]), "r"(a[1]), "r"(a[2]), "r"(a[3]), "r"(b[0]), "r"(b[1]));
}
__device__ __forceinline__ void cp16(void* smem_dst, const void* gsrc) {
    unsigned s = (unsigned)__cvta_generic_to_shared(smem_dst);
    asm volatile("cp.async.cg.shared.global [%0], [%1], 16;\n" :: "r"(s), "l"(gsrc));
}
#define CP_COMMIT() asm volatile("cp.async.commit_group;\n")
#define CP_WAIT(N)  asm volatile("cp.async.wait_group %0;\n" :: "n"(N))

// SMEM layout (bytes). ws0/ws1: double-buffered QKV weight chunks [384][40] half.
// After QKV, qh/kh/vt overlay the dead staging buffers. oh overlays xh.
// NOTE: wp must start AFTER ws1's end (48128+30720=78848) — overlap here was
// the round-2 correctness bug.
#define SM_XH  0       // [64][136] half = 17408   (x fp16)      -> later oh
#define SM_WS0 17408   // [384][40] half = 30720
#define SM_WS1 48128   // [384][40] half = 30720
#define SM_QH  17408   // [64][136] half (overlays ws0)
#define SM_KH  34816   // [64][136] half (overlays ws0 tail / ws1 head)
#define SM_VT  52224   // [128][72] half = 18432 (v transposed vt[d][m], in ws1)
#define SM_OH  0       // [64][136] half (overlays xh)
#define SM_WP  78848   // [128][136] half = 34816  (Wproj, staged once)
#define SMEM_BYTES 113664

// stage one K=32 chunk of Wqkv rows 0..383 into ws (row stride 40 halves)
__device__ __forceinline__ void stage_qkv_chunk(__half* ws, int kb, int tid) {
#pragma unroll
    for (int i = 0; i < 6; ++i) {
        int idx = tid + i * 256;              // 1536 x 16B ops (384 rows x 4)
        int r = idx >> 2, c = idx & 3;
        cp16(ws + r * 40 + c * 8, g_wqkv + r * 128 + kb * 32 + c * 8);
    }
}

// ---------------- main fused kernel: 1 window per CTA ----------------
__global__ void __launch_bounds__(256, 2)
swin_attn_kernel(const float* __restrict__ x,
                 const float* __restrict__ qkv_b,
                 const float* __restrict__ proj_b,
                 float* __restrict__ out) {
    extern __shared__ char smem[];
    __half* xh  = (__half*)(smem + SM_XH);
    __half* ws0 = (__half*)(smem + SM_WS0);
    __half* ws1 = (__half*)(smem + SM_WS1);
    __half* qh  = (__half*)(smem + SM_QH);
    __half* kh  = (__half*)(smem + SM_KH);
    __half* vt  = (__half*)(smem + SM_VT);
    __half* oh  = (__half*)(smem + SM_OH);
    __half* wp  = (__half*)(smem + SM_WP);

    const int tid  = threadIdx.x;
    const int lane = tid & 31;
    const int warp = tid >> 5;
    const int l4   = lane >> 2;
    const int lm   = lane & 3;
    const int b    = blockIdx.x;

    // ---- prologue: async-stage weight chunk 0 (g0) + full Wproj (g1) ----
    stage_qkv_chunk(ws0, 0, tid);
    CP_COMMIT();
#pragma unroll
    for (int i = 0; i < 8; ++i) {
        int idx = tid + i * 256;              // 2048 x 16B: 128 rows x 16 chunks
        int r = idx >> 4, c = idx & 15;
        cp16(wp + r * 136 + c * 8, g_wproj + r * 128 + c * 8);
    }
    CP_COMMIT();

    // ---- phase 0: x tile -> fp16 smem (overlaps with cp.async) ----
    {
        const float4* xg = (const float4*)(x + (size_t)b * NTOK * DIMC);
#pragma unroll
        for (int i = 0; i < 8; ++i) {
            int idx = tid + i * 256;          // 2048 float4
            float4 v = xg[idx];
            int row = idx >> 5;
            int col = (idx & 31) << 2;
            __half2* dst = (__half2*)(xh + row * 136 + col);
            dst[0] = __floats2half2_rn(v.x, v.y);
            dst[1] = __floats2half2_rn(v.z, v.w);
        }
    }

    const int mi = warp & 1;   // M-half (rows mi*32..+31)
    const int ni = warp >> 1;  // N-quarter

    // ---- phase 1: merged QKV GEMM, double-buffered staging ----
    {
        float c[2][8][4];   // q,k part: N cols ni*64 + nt*8
        float cv[2][4][4];  // v part:   N cols 256 + ni*32 + nt*8
#pragma unroll
        for (int a = 0; a < 2; ++a) {
#pragma unroll
            for (int t = 0; t < 8; ++t)
#pragma unroll
                for (int r = 0; r < 4; ++r) c[a][t][r] = 0.f;
#pragma unroll
            for (int t = 0; t < 4; ++t)
#pragma unroll
                for (int r = 0; r < 4; ++r) cv[a][t][r] = 0.f;
        }

#pragma unroll
        for (int kb = 0; kb < 4; ++kb) {
            __half* wsc = (kb & 1) ? ws1 : ws0;
            if (kb < 3) {
                stage_qkv_chunk((kb & 1) ? ws0 : ws1, kb + 1, tid);
                CP_COMMIT();
            }
            if (kb == 0)      CP_WAIT(2);  // pending {c0,wp,c1} -> drain c0
            else if (kb < 3)  CP_WAIT(1);  // drain up to chunk kb
            else              CP_WAIT(0);  // everything (incl. Wproj) done
            __syncthreads();
#pragma unroll
            for (int kt = 0; kt < 2; ++kt) {
                int kc = kb * 32 + kt * 16;
                unsigned a[2][4];
#pragma unroll
                for (int mt = 0; mt < 2; ++mt) {
                    int r0 = mi * 32 + mt * 16 + l4;
                    a[mt][0] = lds_u32(xh + r0 * 136 + kc + lm * 2);
                    a[mt][1] = lds_u32(xh + (r0 + 8) * 136 + kc + lm * 2);
                    a[mt][2] = lds_u32(xh + r0 * 136 + kc + 8 + lm * 2);
                    a[mt][3] = lds_u32(xh + (r0 + 8) * 136 + kc + 8 + lm * 2);
                }
#pragma unroll
                for (int nt = 0; nt < 8; ++nt) {    // q,k rows 0..255
                    int jr = ni * 64 + nt * 8 + l4;
                    unsigned bb[2];
                    bb[0] = lds_u32(wsc + jr * 40 + kt * 16 + lm * 2);
                    bb[1] = lds_u32(wsc + jr * 40 + kt * 16 + 8 + lm * 2);
                    mma_16816(c[0][nt], a[0], bb);
                    mma_16816(c[1][nt], a[1], bb);
                }
#pragma unroll
                for (int nt = 0; nt < 4; ++nt) {    // v rows 256..383
                    int jr = 256 + ni * 32 + nt * 8 + l4;
                    unsigned bb[2];
                    bb[0] = lds_u32(wsc + jr * 40 + kt * 16 + lm * 2);
                    bb[1] = lds_u32(wsc + jr * 40 + kt * 16 + 8 + lm * 2);
                    mma_16816(cv[0][nt], a[0], bb);
                    mma_16816(cv[1][nt], a[1], bb);
                }
            }
            __syncthreads();
        }

        // epilogue: q (scaled) / k -> qh/kh ; v -> vt (transposed)
#pragma unroll
        for (int mt = 0; mt < 2; ++mt)
#pragma unroll
            for (int nt = 0; nt < 8; ++nt) {
                int col = ni * 64 + nt * 8 + lm * 2;
                int r0 = mi * 32 + mt * 16 + l4;
                float2 bv = *(const float2*)(qkv_b + col);
                float s = (col < 128) ? ATT_SCALE : 1.0f;
                __half2 h0 = __floats2half2_rn((c[mt][nt][0] + bv.x) * s,
                                               (c[mt][nt][1] + bv.y) * s);
                __half2 h1 = __floats2half2_rn((c[mt][nt][2] + bv.x) * s,
                                               (c[mt][nt][3] + bv.y) * s);
                __half* base = (col < 128) ? qh : kh;
                int cc = col & 127;
                *(__half2*)(base + r0 * 136 + cc) = h0;
                *(__half2*)(base + (r0 + 8) * 136 + cc) = h1;
            }
#pragma unroll
        for (int mt = 0; mt < 2; ++mt)
#pragma unroll
            for (int nt = 0; nt < 4; ++nt) {
                int d  = ni * 32 + nt * 8 + lm * 2;
                int r0 = mi * 32 + mt * 16 + l4;
                float2 bv = *(const float2*)(qkv_b + 256 + d);
                vt[d * 72 + r0]           = __float2half_rn(cv[mt][nt][0] + bv.x);
                vt[(d + 1) * 72 + r0]     = __float2half_rn(cv[mt][nt][1] + bv.y);
                vt[d * 72 + r0 + 8]       = __float2half_rn(cv[mt][nt][2] + bv.x);
                vt[(d + 1) * 72 + r0 + 8] = __float2half_rn(cv[mt][nt][3] + bv.y);
            }
    }
    __syncthreads();

    // ---- phase 2: attention (2 warps per head) ----
    {
        const int h = warp >> 1;
        const int mh = warp & 1;
        const int rowbase = mh * 32;

        float s[2][8][4];
#pragma unroll
        for (int a = 0; a < 2; ++a)
#pragma unroll
            for (int t = 0; t < 8; ++t)
#pragma unroll
                for (int r = 0; r < 4; ++r) s[a][t][r] = 0.f;

        // S = Q @ K^T (q pre-scaled)
#pragma unroll
        for (int kt = 0; kt < 2; ++kt) {
            int kc = h * 32 + kt * 16;
            unsigned a[2][4];
#pragma unroll
            for (int mt = 0; mt < 2; ++mt) {
                int r0 = rowbase + mt * 16 + l4;
                a[mt][0] = lds_u32(qh + r0 * 136 + kc + lm * 2);
                a[mt][1] = lds_u32(qh + (r0 + 8) * 136 + kc + lm * 2);
                a[mt][2] = lds_u32(qh + r0 * 136 + kc + 8 + lm * 2);
                a[mt][3] = lds_u32(qh + (r0 + 8) * 136 + kc + 8 + lm * 2);
            }
#pragma unroll
            for (int nt = 0; nt < 8; ++nt) {
                int mcol = nt * 8 + l4;
                unsigned bb[2];
                bb[0] = lds_u32(kh + mcol * 136 + kc + lm * 2);
                bb[1] = lds_u32(kh + mcol * 136 + kc + 8 + lm * 2);
                mma_16816(s[0][nt], a[0], bb);
                mma_16816(s[1][nt], a[1], bb);
            }
        }

        // + (bias+mask), softmax
        const float* bm = g_bm + ((size_t)((b & 255) * 4 + h)) * 64 * 64;
        float rmax[4] = {-1e30f, -1e30f, -1e30f, -1e30f};
#pragma unroll
        for (int mt = 0; mt < 2; ++mt) {
            int r0 = rowbase + mt * 16 + l4;
#pragma unroll
            for (int nt = 0; nt < 8; ++nt) {
                int col = nt * 8 + lm * 2;
                float2 b0 = *(const float2*)(bm + r0 * 64 + col);
                float2 b1 = *(const float2*)(bm + (r0 + 8) * 64 + col);
                s[mt][nt][0] += b0.x;
                s[mt][nt][1] += b0.y;
                s[mt][nt][2] += b1.x;
                s[mt][nt][3] += b1.y;
                rmax[mt * 2]     = fmaxf(rmax[mt * 2],     fmaxf(s[mt][nt][0], s[mt][nt][1]));
                rmax[mt * 2 + 1] = fmaxf(rmax[mt * 2 + 1], fmaxf(s[mt][nt][2], s[mt][nt][3]));
            }
        }
#pragma unroll
        for (int i = 0; i < 4; ++i) {
            rmax[i] = fmaxf(rmax[i], __shfl_xor_sync(0xffffffffu, rmax[i], 1));
            rmax[i] = fmaxf(rmax[i], __shfl_xor_sync(0xffffffffu, rmax[i], 2));
        }
        float rsum[4] = {0.f, 0.f, 0.f, 0.f};
#pragma unroll
        for (int mt = 0; mt < 2; ++mt)
#pragma unroll
            for (int nt = 0; nt < 8; ++nt) {
                s[mt][nt][0] = __expf(s[mt][nt][0] - rmax[mt * 2]);
                s[mt][nt][1] = __expf(s[mt][nt][1] - rmax[mt * 2]);
                s[mt][nt][2] = __expf(s[mt][nt][2] - rmax[mt * 2 + 1]);
                s[mt][nt][3] = __expf(s[mt][nt][3] - rmax[mt * 2 + 1]);
                rsum[mt * 2]     += s[mt][nt][0] + s[mt][nt][1];
                rsum[mt * 2 + 1] += s[mt][nt][2] + s[mt][nt][3];
            }
#pragma unroll
        for (int i = 0; i < 4; ++i) {
            rsum[i] += __shfl_xor_sync(0xffffffffu, rsum[i], 1);
            rsum[i] += __shfl_xor_sync(0xffffffffu, rsum[i], 2);
        }
        float rinv[4];
#pragma unroll
        for (int i = 0; i < 4; ++i) rinv[i] = 1.0f / rsum[i];

        // repack normalized P into A fragments
        unsigned pa[2][4][4];
#pragma unroll
        for (int mt = 0; mt < 2; ++mt)
#pragma unroll
            for (int k2 = 0; k2 < 4; ++k2) {
                pa[mt][k2][0] = h2u(__floats2half2_rn(s[mt][2 * k2][0] * rinv[2 * mt],
                                                      s[mt][2 * k2][1] * rinv[2 * mt]));
                pa[mt][k2][1] = h2u(__floats2half2_rn(s[mt][2 * k2][2] * rinv[2 * mt + 1],
                                                      s[mt][2 * k2][3] * rinv[2 * mt + 1]));
                pa[mt][k2][2] = h2u(__floats2half2_rn(s[mt][2 * k2 + 1][0] * rinv[2 * mt],
                                                      s[mt][2 * k2 + 1][1] * rinv[2 * mt]));
                pa[mt][k2][3] = h2u(__floats2half2_rn(s[mt][2 * k2 + 1][2] * rinv[2 * mt + 1],
                                                      s[mt][2 * k2 + 1][3] * rinv[2 * mt + 1]));
            }

        // O = P @ V
        float o[2][4][4];
#pragma unroll
        for (int a = 0; a < 2; ++a)
#pragma unroll
            for (int t = 0; t < 4; ++t)
#pragma unroll
                for (int r = 0; r < 4; ++r) o[a][t][r] = 0.f;
#pragma unroll
        for (int k2 = 0; k2 < 4; ++k2)
#pragma unroll
            for (int nt = 0; nt < 4; ++nt) {
                int dd = nt * 8 + l4;
                unsigned bb[2];
                bb[0] = lds_u32(vt + (h * 32 + dd) * 72 + k2 * 16 + lm * 2);
                bb[1] = lds_u32(vt + (h * 32 + dd) * 72 + k2 * 16 + 8 + lm * 2);
                mma_16816(o[0][nt], pa[0][k2], bb);
                mma_16816(o[1][nt], pa[1][k2], bb);
            }
#pragma unroll
        for (int mt = 0; mt < 2; ++mt)
#pragma unroll
            for (int nt = 0; nt < 4; ++nt) {
                int col = h * 32 + nt * 8 + lm * 2;
                int r0 = rowbase + mt * 16 + l4;
                *(__half2*)(oh + r0 * 136 + col) =
                    __floats2half2_rn(o[mt][nt][0], o[mt][nt][1]);
                *(__half2*)(oh + (r0 + 8) * 136 + col) =
                    __floats2half2_rn(o[mt][nt][2], o[mt][nt][3]);
            }
    }
    __syncthreads();

    // ---- phase 3: out = O @ Wproj^T + proj_b  (Wproj already resident) ----
    {
        float c[2][4][4];
#pragma unroll
        for (int a = 0; a < 2; ++a)
#pragma unroll
            for (int t = 0; t < 4; ++t)
#pragma unroll
                for (int r = 0; r < 4; ++r) c[a][t][r] = 0.f;

#pragma unroll
        for (int kt = 0; kt < 8; ++kt) {
            int kc = kt * 16;
            unsigned a[2][4];
#pragma unroll
            for (int mt = 0; mt < 2; ++mt) {
                int r0 = mi * 32 + mt * 16 + l4;
                a[mt][0] = lds_u32(oh + r0 * 136 + kc + lm * 2);
                a[mt][1] = lds_u32(oh + (r0 + 8) * 136 + kc + lm * 2);
                a[mt][2] = lds_u32(oh + r0 * 136 + kc + 8 + lm * 2);
                a[mt][3] = lds_u32(oh + (r0 + 8) * 136 + kc + 8 + lm * 2);
            }
#pragma unroll
            for (int nt = 0; nt < 4; ++nt) {
                int jr = ni * 32 + nt * 8 + l4;
                unsigned bb[2];
                bb[0] = lds_u32(wp + jr * 136 + kc + lm * 2);
                bb[1] = lds_u32(wp + jr * 136 + kc + 8 + lm * 2);
                mma_16816(c[0][nt], a[0], bb);
                mma_16816(c[1][nt], a[1], bb);
            }
        }

        float* og = out + (size_t)b * NTOK * DIMC;
#pragma unroll
        for (int mt = 0; mt < 2; ++mt)
#pragma unroll
            for (int nt = 0; nt < 4; ++nt) {
                int col = ni * 32 + nt * 8 + lm * 2;
                int r0 = mi * 32 + mt * 16 + l4;
                float2 pb = *(const float2*)(proj_b + col);
                float2 v0 = {c[mt][nt][0] + pb.x, c[mt][nt][1] + pb.y};
                float2 v1 = {c[mt][nt][2] + pb.x, c[mt][nt][3] + pb.y};
                *(float2*)(og + r0 * 128 + col) = v0;
                *(float2*)(og + (r0 + 8) * 128 + col) = v1;
            }
    }
}

// ---------------- launch ----------------
extern "C" void kernel_launch(void* const* d_in, const int* in_sizes, int n_in,
                              void* d_out, int out_size) {
    const float* x       = (const float*)d_in[0];
    const float* mask    = (const float*)d_in[1];
    const float* qkv_w   = (const float*)d_in[2];
    const float* qkv_b   = (const float*)d_in[3];
    const float* proj_w  = (const float*)d_in[4];
    const float* proj_b  = (const float*)d_in[5];
    const float* bias_t  = (const float*)d_in[6];
    const int*   rel_idx = (const int*)d_in[7];
    float* out = (float*)d_out;

    prep_all_k<<<(NWIN * NHEADS * NTOK * NTOK) / 256, 256>>>(mask, bias_t, rel_idx,
                                                             qkv_w, proj_w);

    cudaFuncSetAttribute(swin_attn_kernel,
                         cudaFuncAttributeMaxDynamicSharedMemorySize, SMEM_BYTES);
    swin_attn_kernel<<<NWINDOWS, 256, SMEM_BYTES>>>(x, qkv_b, proj_b, out);
}

// round 4
// speedup vs baseline: 1.2315x; 1.0330x over previous
#include <cuda_runtime.h>
#include <cuda_fp16.h>

#define NTOK      64
#define DIMC      128
#define NHEADS    4
#define NWIN      256
#define NWINDOWS  8192
#define ATT_SCALE 0.17677669529663687f

// ---------------- device scratch ----------------
__device__ __half g_wqkv[3 * DIMC * DIMC];           // [384][128] fp16
__device__ __half g_wproj[DIMC * DIMC];              // [128][128] fp16
__device__ float  g_bm[NWIN * NHEADS * NTOK * NTOK]; // [w][h][n][m] bias+mask

// ---------------- merged prep kernel ----------------
__global__ void prep_all_k(const float* __restrict__ mask,
                           const float* __restrict__ bias_table,
                           const int* __restrict__ rel_index,
                           const float* __restrict__ qkv_w,
                           const float* __restrict__ proj_w) {
    int e = blockIdx.x * blockDim.x + threadIdx.x;
    if (e < 3 * DIMC * DIMC) g_wqkv[e] = __float2half_rn(qkv_w[e]);
    if (e < DIMC * DIMC)     g_wproj[e] = __float2half_rn(proj_w[e]);
    int m = e & 63, n = (e >> 6) & 63, h = (e >> 12) & 3, w = e >> 14;
    g_bm[e] = mask[(w * 64 + n) * 64 + m]
            + bias_table[rel_index[n * 64 + m] * NHEADS + h];
}

// ---------------- helpers ----------------
__device__ __forceinline__ unsigned h2u(__half2 v) {
    return *reinterpret_cast<unsigned*>(&v);
}
__device__ __forceinline__ void mma_16816(float c[4], const unsigned a[4],
                                          const unsigned b[2]) {
    asm volatile(
        "mma.sync.aligned.m16n8k16.row.col.f32.f16.f16.f32 "
        "{%0,%1,%2,%3}, {%4,%5,%6,%7}, {%8,%9}, {%0,%1,%2,%3};\n"
        : "+f"(c[0]), "+f"(c[1]), "+f"(c[2]), "+f"(c[3])
        : "r"(a[0]), "r"(a[1]), "r"(a[2]), "r"(a[3]), "r"(b[0]), "r"(b[1]));
}
// ldmatrix x4: p is this lane's row pointer (16B-aligned row segment)
__device__ __forceinline__ void ldsm4(unsigned r[4], const __half* p) {
    unsigned a = (unsigned)__cvta_generic_to_shared(p);
    asm volatile("ldmatrix.sync.aligned.m8n8.x4.shared.b16 {%0,%1,%2,%3}, [%4];\n"
                 : "=r"(r[0]), "=r"(r[1]), "=r"(r[2]), "=r"(r[3]) : "r"(a));
}
__device__ __forceinline__ void cp16(void* smem_dst, const void* gsrc) {
    unsigned s = (unsigned)__cvta_generic_to_shared(smem_dst);
    asm volatile("cp.async.cg.shared.global [%0], [%1], 16;\n" :: "r"(s), "l"(gsrc));
}
#define CP_COMMIT() asm volatile("cp.async.commit_group;\n")
#define CP_WAIT(N)  asm volatile("cp.async.wait_group %0;\n" :: "n"(N))

// SMEM layout (bytes); wp strictly after ws1 (R2 bug).
#define SM_XH  0       // [64][136] half = 17408  -> later oh
#define SM_WS0 17408   // [384][40] half = 30720
#define SM_WS1 48128   // [384][40] half = 30720
#define SM_QH  17408   // [64][136] half (overlays ws0)
#define SM_KH  34816   // [64][136] half
#define SM_VT  52224   // [128][72] half = 18432 (vt[d][m])
#define SM_OH  0       // [64][136] half (overlays xh)
#define SM_WP  78848   // [128][136] half = 34816
#define SMEM_BYTES 113664

__device__ __forceinline__ void stage_qkv_chunk(__half* ws, int kb, int tid) {
#pragma unroll
    for (int i = 0; i < 6; ++i) {
        int idx = tid + i * 256;              // 1536 x 16B (384 rows x 4)
        int r = idx >> 2, c = idx & 3;
        cp16(ws + r * 40 + c * 8, g_wqkv + r * 128 + kb * 32 + c * 8);
    }
}

// ---------------- main fused kernel: 1 window per CTA ----------------
__global__ void __launch_bounds__(256, 2)
swin_attn_kernel(const float* __restrict__ x,
                 const float* __restrict__ qkv_b,
                 const float* __restrict__ proj_b,
                 float* __restrict__ out) {
    extern __shared__ char smem[];
    __half* xh  = (__half*)(smem + SM_XH);
    __half* ws0 = (__half*)(smem + SM_WS0);
    __half* ws1 = (__half*)(smem + SM_WS1);
    __half* qh  = (__half*)(smem + SM_QH);
    __half* kh  = (__half*)(smem + SM_KH);
    __half* vt  = (__half*)(smem + SM_VT);
    __half* oh  = (__half*)(smem + SM_OH);
    __half* wp  = (__half*)(smem + SM_WP);

    const int tid  = threadIdx.x;
    const int lane = tid & 31;
    const int warp = tid >> 5;
    const int l4   = lane >> 2;
    const int lm   = lane & 3;
    const int b    = blockIdx.x;

    // ldmatrix per-lane row/col selectors
    const int arow = (lane & 7) + (lane & 8);          // A x4: 16 rows
    const int acol = (lane & 16) ? 8 : 0;              // A x4: k halves
    const int brow = (lane & 7) + ((lane & 16) ? 8 : 0); // B x4: 16 n-rows
    const int bcol = (lane & 8) ? 8 : 0;               // B x4: k halves

    // ---- prologue: async-stage chunk 0 (g0) + full Wproj (g1) ----
    stage_qkv_chunk(ws0, 0, tid);
    CP_COMMIT();
#pragma unroll
    for (int i = 0; i < 8; ++i) {
        int idx = tid + i * 256;              // 2048 x 16B
        int r = idx >> 4, c = idx & 15;
        cp16(wp + r * 136 + c * 8, g_wproj + r * 128 + c * 8);
    }
    CP_COMMIT();

    // ---- phase 0: x tile -> fp16 smem ----
    {
        const float4* xg = (const float4*)(x + (size_t)b * NTOK * DIMC);
#pragma unroll
        for (int i = 0; i < 8; ++i) {
            int idx = tid + i * 256;
            float4 v = xg[idx];
            int row = idx >> 5;
            int col = (idx & 31) << 2;
            __half2* dst = (__half2*)(xh + row * 136 + col);
            dst[0] = __floats2half2_rn(v.x, v.y);
            dst[1] = __floats2half2_rn(v.z, v.w);
        }
    }

    const int mi = warp & 1;   // M-half
    const int ni = warp >> 1;  // N-quarter

    // ---- phase 1: merged QKV GEMM, double-buffered staging ----
    {
        float c[2][8][4];   // q,k: N cols ni*64 + nt*8
        float cv[2][4][4];  // v:   N cols 256 + ni*32 + nt*8
#pragma unroll
        for (int a = 0; a < 2; ++a) {
#pragma unroll
            for (int t = 0; t < 8; ++t)
#pragma unroll
                for (int r = 0; r < 4; ++r) c[a][t][r] = 0.f;
#pragma unroll
            for (int t = 0; t < 4; ++t)
#pragma unroll
                for (int r = 0; r < 4; ++r) cv[a][t][r] = 0.f;
        }

#pragma unroll
        for (int kb = 0; kb < 4; ++kb) {
            __half* wsc = (kb & 1) ? ws1 : ws0;
            if (kb < 3) {
                stage_qkv_chunk((kb & 1) ? ws0 : ws1, kb + 1, tid);
                CP_COMMIT();
            }
            if (kb == 0)      CP_WAIT(2);
            else if (kb < 3)  CP_WAIT(1);
            else              CP_WAIT(0);
            __syncthreads();
#pragma unroll
            for (int kt = 0; kt < 2; ++kt) {
                int kc = kb * 32 + kt * 16;
                unsigned a0[4], a1[4];
                ldsm4(a0, xh + (mi * 32 + arow) * 136 + kc + acol);
                ldsm4(a1, xh + (mi * 32 + 16 + arow) * 136 + kc + acol);
#pragma unroll
                for (int p = 0; p < 4; ++p) {   // q,k rows: 2 n-blocks per x4
                    unsigned r[4];
                    ldsm4(r, wsc + (ni * 64 + p * 16 + brow) * 40 + kt * 16 + bcol);
                    mma_16816(c[0][2 * p],     a0, r);
                    mma_16816(c[1][2 * p],     a1, r);
                    mma_16816(c[0][2 * p + 1], a0, r + 2);
                    mma_16816(c[1][2 * p + 1], a1, r + 2);
                }
#pragma unroll
                for (int p = 0; p < 2; ++p) {   // v rows
                    unsigned r[4];
                    ldsm4(r, wsc + (256 + ni * 32 + p * 16 + brow) * 40 + kt * 16 + bcol);
                    mma_16816(cv[0][2 * p],     a0, r);
                    mma_16816(cv[1][2 * p],     a1, r);
                    mma_16816(cv[0][2 * p + 1], a0, r + 2);
                    mma_16816(cv[1][2 * p + 1], a1, r + 2);
                }
            }
            __syncthreads();
        }

        // epilogue: q (scaled) / k -> qh/kh ; v -> vt (transposed)
#pragma unroll
        for (int mt = 0; mt < 2; ++mt)
#pragma unroll
            for (int nt = 0; nt < 8; ++nt) {
                int col = ni * 64 + nt * 8 + lm * 2;
                int r0 = mi * 32 + mt * 16 + l4;
                float2 bv = *(const float2*)(qkv_b + col);
                float s = (col < 128) ? ATT_SCALE : 1.0f;
                __half2 h0 = __floats2half2_rn((c[mt][nt][0] + bv.x) * s,
                                               (c[mt][nt][1] + bv.y) * s);
                __half2 h1 = __floats2half2_rn((c[mt][nt][2] + bv.x) * s,
                                               (c[mt][nt][3] + bv.y) * s);
                __half* base = (col < 128) ? qh : kh;
                int cc = col & 127;
                *(__half2*)(base + r0 * 136 + cc) = h0;
                *(__half2*)(base + (r0 + 8) * 136 + cc) = h1;
            }
#pragma unroll
        for (int mt = 0; mt < 2; ++mt)
#pragma unroll
            for (int nt = 0; nt < 4; ++nt) {
                int d  = ni * 32 + nt * 8 + lm * 2;
                int r0 = mi * 32 + mt * 16 + l4;
                float2 bv = *(const float2*)(qkv_b + 256 + d);
                vt[d * 72 + r0]           = __float2half_rn(cv[mt][nt][0] + bv.x);
                vt[(d + 1) * 72 + r0]     = __float2half_rn(cv[mt][nt][1] + bv.y);
                vt[d * 72 + r0 + 8]       = __float2half_rn(cv[mt][nt][2] + bv.x);
                vt[(d + 1) * 72 + r0 + 8] = __float2half_rn(cv[mt][nt][3] + bv.y);
            }
    }
    __syncthreads();

    // ---- phase 2: attention (2 warps per head) ----
    {
        const int h = warp >> 1;
        const int mh = warp & 1;
        const int rowbase = mh * 32;

        float s[2][8][4];
#pragma unroll
        for (int a = 0; a < 2; ++a)
#pragma unroll
            for (int t = 0; t < 8; ++t)
#pragma unroll
                for (int r = 0; r < 4; ++r) s[a][t][r] = 0.f;

        // S = Q @ K^T (q pre-scaled)
#pragma unroll
        for (int kt = 0; kt < 2; ++kt) {
            int kc = h * 32 + kt * 16;
            unsigned a0[4], a1[4];
            ldsm4(a0, qh + (rowbase + arow) * 136 + kc + acol);
            ldsm4(a1, qh + (rowbase + 16 + arow) * 136 + kc + acol);
#pragma unroll
            for (int p = 0; p < 4; ++p) {
                unsigned r[4];
                ldsm4(r, kh + (p * 16 + brow) * 136 + kc + bcol);
                mma_16816(s[0][2 * p],     a0, r);
                mma_16816(s[1][2 * p],     a1, r);
                mma_16816(s[0][2 * p + 1], a0, r + 2);
                mma_16816(s[1][2 * p + 1], a1, r + 2);
            }
        }

        // + (bias+mask), softmax
        const float* bm = g_bm + ((size_t)((b & 255) * 4 + h)) * 64 * 64;
        float rmax[4] = {-1e30f, -1e30f, -1e30f, -1e30f};
#pragma unroll
        for (int mt = 0; mt < 2; ++mt) {
            int r0 = rowbase + mt * 16 + l4;
#pragma unroll
            for (int nt = 0; nt < 8; ++nt) {
                int col = nt * 8 + lm * 2;
                float2 b0 = *(const float2*)(bm + r0 * 64 + col);
                float2 b1 = *(const float2*)(bm + (r0 + 8) * 64 + col);
                s[mt][nt][0] += b0.x;
                s[mt][nt][1] += b0.y;
                s[mt][nt][2] += b1.x;
                s[mt][nt][3] += b1.y;
                rmax[mt * 2]     = fmaxf(rmax[mt * 2],     fmaxf(s[mt][nt][0], s[mt][nt][1]));
                rmax[mt * 2 + 1] = fmaxf(rmax[mt * 2 + 1], fmaxf(s[mt][nt][2], s[mt][nt][3]));
            }
        }
#pragma unroll
        for (int i = 0; i < 4; ++i) {
            rmax[i] = fmaxf(rmax[i], __shfl_xor_sync(0xffffffffu, rmax[i], 1));
            rmax[i] = fmaxf(rmax[i], __shfl_xor_sync(0xffffffffu, rmax[i], 2));
        }
        float rsum[4] = {0.f, 0.f, 0.f, 0.f};
#pragma unroll
        for (int mt = 0; mt < 2; ++mt)
#pragma unroll
            for (int nt = 0; nt < 8; ++nt) {
                s[mt][nt][0] = __expf(s[mt][nt][0] - rmax[mt * 2]);
                s[mt][nt][1] = __expf(s[mt][nt][1] - rmax[mt * 2]);
                s[mt][nt][2] = __expf(s[mt][nt][2] - rmax[mt * 2 + 1]);
                s[mt][nt][3] = __expf(s[mt][nt][3] - rmax[mt * 2 + 1]);
                rsum[mt * 2]     += s[mt][nt][0] + s[mt][nt][1];
                rsum[mt * 2 + 1] += s[mt][nt][2] + s[mt][nt][3];
            }
#pragma unroll
        for (int i = 0; i < 4; ++i) {
            rsum[i] += __shfl_xor_sync(0xffffffffu, rsum[i], 1);
            rsum[i] += __shfl_xor_sync(0xffffffffu, rsum[i], 2);
        }
        float rinv[4];
#pragma unroll
        for (int i = 0; i < 4; ++i) rinv[i] = 1.0f / rsum[i];

        // repack normalized P into A fragments
        unsigned pa[2][4][4];
#pragma unroll
        for (int mt = 0; mt < 2; ++mt)
#pragma unroll
            for (int k2 = 0; k2 < 4; ++k2) {
                pa[mt][k2][0] = h2u(__floats2half2_rn(s[mt][2 * k2][0] * rinv[2 * mt],
                                                      s[mt][2 * k2][1] * rinv[2 * mt]));
                pa[mt][k2][1] = h2u(__floats2half2_rn(s[mt][2 * k2][2] * rinv[2 * mt + 1],
                                                      s[mt][2 * k2][3] * rinv[2 * mt + 1]));
                pa[mt][k2][2] = h2u(__floats2half2_rn(s[mt][2 * k2 + 1][0] * rinv[2 * mt],
                                                      s[mt][2 * k2 + 1][1] * rinv[2 * mt]));
                pa[mt][k2][3] = h2u(__floats2half2_rn(s[mt][2 * k2 + 1][2] * rinv[2 * mt + 1],
                                                      s[mt][2 * k2 + 1][3] * rinv[2 * mt + 1]));
            }

        // O = P @ V
        float o[2][4][4];
#pragma unroll
        for (int a = 0; a < 2; ++a)
#pragma unroll
            for (int t = 0; t < 4; ++t)
#pragma unroll
                for (int r = 0; r < 4; ++r) o[a][t][r] = 0.f;
#pragma unroll
        for (int k2 = 0; k2 < 4; ++k2)
#pragma unroll
            for (int p = 0; p < 2; ++p) {
                unsigned r[4];
                ldsm4(r, vt + (h * 32 + p * 16 + brow) * 72 + k2 * 16 + bcol);
                mma_16816(o[0][2 * p],     pa[0][k2], r);
                mma_16816(o[1][2 * p],     pa[1][k2], r);
                mma_16816(o[0][2 * p + 1], pa[0][k2], r + 2);
                mma_16816(o[1][2 * p + 1], pa[1][k2], r + 2);
            }
#pragma unroll
        for (int mt = 0; mt < 2; ++mt)
#pragma unroll
            for (int nt = 0; nt < 4; ++nt) {
                int col = h * 32 + nt * 8 + lm * 2;
                int r0 = rowbase + mt * 16 + l4;
                *(__half2*)(oh + r0 * 136 + col) =
                    __floats2half2_rn(o[mt][nt][0], o[mt][nt][1]);
                *(__half2*)(oh + (r0 + 8) * 136 + col) =
                    __floats2half2_rn(o[mt][nt][2], o[mt][nt][3]);
            }
    }
    __syncthreads();

    // ---- phase 3: out = O @ Wproj^T + proj_b (Wproj resident) ----
    {
        float c[2][4][4];
#pragma unroll
        for (int a = 0; a < 2; ++a)
#pragma unroll
            for (int t = 0; t < 4; ++t)
#pragma unroll
                for (int r = 0; r < 4; ++r) c[a][t][r] = 0.f;

#pragma unroll
        for (int kt = 0; kt < 8; ++kt) {
            int kc = kt * 16;
            unsigned a0[4], a1[4];
            ldsm4(a0, oh + (mi * 32 + arow) * 136 + kc + acol);
            ldsm4(a1, oh + (mi * 32 + 16 + arow) * 136 + kc + acol);
#pragma unroll
            for (int p = 0; p < 2; ++p) {
                unsigned r[4];
                ldsm4(r, wp + (ni * 32 + p * 16 + brow) * 136 + kc + bcol);
                mma_16816(c[0][2 * p],     a0, r);
                mma_16816(c[1][2 * p],     a1, r);
                mma_16816(c[0][2 * p + 1], a0, r + 2);
                mma_16816(c[1][2 * p + 1], a1, r + 2);
            }
        }

        float* og = out + (size_t)b * NTOK * DIMC;
#pragma unroll
        for (int mt = 0; mt < 2; ++mt)
#pragma unroll
            for (int nt = 0; nt < 4; ++nt) {
                int col = ni * 32 + nt * 8 + lm * 2;
                int r0 = mi * 32 + mt * 16 + l4;
                float2 pb = *(const float2*)(proj_b + col);
                float2 v0 = {c[mt][nt][0] + pb.x, c[mt][nt][1] + pb.y};
                float2 v1 = {c[mt][nt][2] + pb.x, c[mt][nt][3] + pb.y};
                *(float2*)(og + r0 * 128 + col) = v0;
                *(float2*)(og + (r0 + 8) * 128 + col) = v1;
            }
    }
}

// ---------------- launch ----------------
extern "C" void kernel_launch(void* const* d_in, const int* in_sizes, int n_in,
                              void* d_out, int out_size) {
    const float* x       = (const float*)d_in[0];
    const float* mask    = (const float*)d_in[1];
    const float* qkv_w   = (const float*)d_in[2];
    const float* qkv_b   = (const float*)d_in[3];
    const float* proj_w  = (const float*)d_in[4];
    const float* proj_b  = (const float*)d_in[5];
    const float* bias_t  = (const float*)d_in[6];
    const int*   rel_idx = (const int*)d_in[7];
    float* out = (float*)d_out;

    prep_all_k<<<(NWIN * NHEADS * NTOK * NTOK) / 256, 256>>>(mask, bias_t, rel_idx,
                                                             qkv_w, proj_w);

    cudaFuncSetAttribute(swin_attn_kernel,
                         cudaFuncAttributeMaxDynamicSharedMemorySize, SMEM_BYTES);
    swin_attn_kernel<<<NWINDOWS, 256, SMEM_BYTES>>>(x, qkv_b, proj_b, out);
}

// round 5
// speedup vs baseline: 1.4637x; 1.1886x over previous
#include <cuda_runtime.h>
#include <cuda_fp16.h>

#define NTOK      64
#define DIMC      128
#define NHEADS    4
#define NWIN      256
#define NWINDOWS  8192
#define ATT_SCALE 0.17677669529663687f

// ---------------- device scratch ----------------
// Fragment-packed weights: index [nb][kt][lane] -> uint2 {b0,b1}
// b0 = {W[n][k0], W[n][k0+1]}, b1 = {W[n][k0+8], W[n][k0+9]},
// n = nb*8 + (lane>>2), k0 = kt*16 + 2*(lane&3).
__device__ uint2 g_wqkvf[48 * 8 * 32];               // 384 rows -> 48 n-blocks
__device__ uint2 g_wprojf[16 * 8 * 32];              // 128 rows -> 16 n-blocks
__device__ float g_bm[NWIN * NHEADS * NTOK * NTOK];  // [w][h][n][m] bias+mask

// ---------------- merged prep kernel ----------------
__global__ void prep_all_k(const float* __restrict__ mask,
                           const float* __restrict__ bias_table,
                           const int* __restrict__ rel_index,
                           const float* __restrict__ qkv_w,
                           const float* __restrict__ proj_w) {
    int e = blockIdx.x * blockDim.x + threadIdx.x;
    // fragment-pack qkv weights
    if (e < 48 * 8 * 32) {
        int lane = e & 31, kt = (e >> 5) & 7, nb = e >> 8;
        int n  = nb * 8 + (lane >> 2);
        int k0 = kt * 16 + 2 * (lane & 3);
        const float* W = qkv_w + n * DIMC + k0;
        __half2 b0 = __floats2half2_rn(W[0], W[1]);
        __half2 b1 = __floats2half2_rn(W[8], W[9]);
        g_wqkvf[e] = make_uint2(*(unsigned*)&b0, *(unsigned*)&b1);
    }
    // fragment-pack proj weights
    if (e < 16 * 8 * 32) {
        int lane = e & 31, kt = (e >> 5) & 7, nb = e >> 8;
        int n  = nb * 8 + (lane >> 2);
        int k0 = kt * 16 + 2 * (lane & 3);
        const float* W = proj_w + n * DIMC + k0;
        __half2 b0 = __floats2half2_rn(W[0], W[1]);
        __half2 b1 = __floats2half2_rn(W[8], W[9]);
        g_wprojf[e] = make_uint2(*(unsigned*)&b0, *(unsigned*)&b1);
    }
    // bias+mask table, e linear over [w][h][n][m]
    int m = e & 63, n = (e >> 6) & 63, h = (e >> 12) & 3, w = e >> 14;
    g_bm[e] = mask[(w * 64 + n) * 64 + m]
            + bias_table[rel_index[n * 64 + m] * NHEADS + h];
}

// ---------------- helpers ----------------
__device__ __forceinline__ unsigned h2u(__half2 v) {
    return *reinterpret_cast<unsigned*>(&v);
}
__device__ __forceinline__ void mma_16816(float c[4], const unsigned a[4],
                                          const unsigned b0, const unsigned b1) {
    asm volatile(
        "mma.sync.aligned.m16n8k16.row.col.f32.f16.f16.f32 "
        "{%0,%1,%2,%3}, {%4,%5,%6,%7}, {%8,%9}, {%0,%1,%2,%3};\n"
        : "+f"(c[0]), "+f"(c[1]), "+f"(c[2]), "+f"(c[3])
        : "r"(a[0]), "r"(a[1]), "r"(a[2]), "r"(a[3]), "r"(b0), "r"(b1));
}
__device__ __forceinline__ void ldsm4(unsigned r[4], const __half* p) {
    unsigned a = (unsigned)__cvta_generic_to_shared(p);
    asm volatile("ldmatrix.sync.aligned.m8n8.x4.shared.b16 {%0,%1,%2,%3}, [%4];\n"
                 : "=r"(r[0]), "=r"(r[1]), "=r"(r[2]), "=r"(r[3]) : "r"(a));
}

// SMEM layout (bytes): no weight staging anymore.
#define SM_XH  0       // [64][136] half = 17408  -> later oh
#define SM_QH  17408   // [64][136] half
#define SM_KH  34816   // [64][136] half
#define SM_VT  52224   // [128][72] half = 18432 (vt[d][m])
#define SM_OH  0       // overlays xh
#define SMEM_BYTES 70656

// ---------------- main fused kernel: 1 window per CTA ----------------
__global__ void __launch_bounds__(256, 2)
swin_attn_kernel(const float* __restrict__ x,
                 const float* __restrict__ qkv_b,
                 const float* __restrict__ proj_b,
                 float* __restrict__ out) {
    extern __shared__ char smem[];
    __half* xh = (__half*)(smem + SM_XH);
    __half* qh = (__half*)(smem + SM_QH);
    __half* kh = (__half*)(smem + SM_KH);
    __half* vt = (__half*)(smem + SM_VT);
    __half* oh = (__half*)(smem + SM_OH);

    const int tid  = threadIdx.x;
    const int lane = tid & 31;
    const int warp = tid >> 5;
    const int l4   = lane >> 2;
    const int lm   = lane & 3;
    const int b    = blockIdx.x;

    // ldmatrix per-lane selectors (A x4 over 16 rows, k16)
    const int arow = (lane & 7) + (lane & 8);
    const int acol = (lane & 16) ? 8 : 0;
    const int brow = (lane & 7) + ((lane & 16) ? 8 : 0);
    const int bcol = (lane & 8) ? 8 : 0;

    // ---- phase 0: x tile -> fp16 smem (streaming loads) ----
    {
        const float4* xg = (const float4*)(x + (size_t)b * NTOK * DIMC);
#pragma unroll
        for (int i = 0; i < 8; ++i) {
            int idx = tid + i * 256;          // 2048 float4
            float4 v = __ldcs(xg + idx);
            int row = idx >> 5;
            int col = (idx & 31) << 2;
            __half2* dst = (__half2*)(xh + row * 136 + col);
            dst[0] = __floats2half2_rn(v.x, v.y);
            dst[1] = __floats2half2_rn(v.z, v.w);
        }
    }
    __syncthreads();   // sync #1

    const int mi = warp & 1;   // M-half
    const int ni = warp >> 1;  // N-quarter

    // ---- phase 1: QKV GEMM, B-frags via coalesced LDG (L1-resident) ----
    {
        float c[2][8][4];   // q,k: N cols ni*64 + nt*8   (nb = ni*8+nt)
        float cv[2][4][4];  // v:   N cols 256+ni*32+nt*8 (nb = 32+ni*4+nt)
#pragma unroll
        for (int a = 0; a < 2; ++a) {
#pragma unroll
            for (int t = 0; t < 8; ++t)
#pragma unroll
                for (int r = 0; r < 4; ++r) c[a][t][r] = 0.f;
#pragma unroll
            for (int t = 0; t < 4; ++t)
#pragma unroll
                for (int r = 0; r < 4; ++r) cv[a][t][r] = 0.f;
        }

#pragma unroll
        for (int ktg = 0; ktg < 8; ++ktg) {
            int kc = ktg * 16;
            unsigned a0[4], a1[4];
            ldsm4(a0, xh + (mi * 32 + arow) * 136 + kc + acol);
            ldsm4(a1, xh + (mi * 32 + 16 + arow) * 136 + kc + acol);
#pragma unroll
            for (int nt = 0; nt < 8; ++nt) {
                uint2 f = g_wqkvf[(((ni * 8 + nt) * 8 + ktg) << 5) + lane];
                mma_16816(c[0][nt], a0, f.x, f.y);
                mma_16816(c[1][nt], a1, f.x, f.y);
            }
#pragma unroll
            for (int nt = 0; nt < 4; ++nt) {
                uint2 f = g_wqkvf[(((32 + ni * 4 + nt) * 8 + ktg) << 5) + lane];
                mma_16816(cv[0][nt], a0, f.x, f.y);
                mma_16816(cv[1][nt], a1, f.x, f.y);
            }
        }

        // epilogue: q (scaled) / k -> qh/kh ; v -> vt (transposed)
#pragma unroll
        for (int mt = 0; mt < 2; ++mt)
#pragma unroll
            for (int nt = 0; nt < 8; ++nt) {
                int col = ni * 64 + nt * 8 + lm * 2;
                int r0 = mi * 32 + mt * 16 + l4;
                float2 bv = *(const float2*)(qkv_b + col);
                float s = (col < 128) ? ATT_SCALE : 1.0f;
                __half2 h0 = __floats2half2_rn((c[mt][nt][0] + bv.x) * s,
                                               (c[mt][nt][1] + bv.y) * s);
                __half2 h1 = __floats2half2_rn((c[mt][nt][2] + bv.x) * s,
                                               (c[mt][nt][3] + bv.y) * s);
                __half* base = (col < 128) ? qh : kh;
                int cc = col & 127;
                *(__half2*)(base + r0 * 136 + cc) = h0;
                *(__half2*)(base + (r0 + 8) * 136 + cc) = h1;
            }
#pragma unroll
        for (int mt = 0; mt < 2; ++mt)
#pragma unroll
            for (int nt = 0; nt < 4; ++nt) {
                int d  = ni * 32 + nt * 8 + lm * 2;
                int r0 = mi * 32 + mt * 16 + l4;
                float2 bv = *(const float2*)(qkv_b + 256 + d);
                vt[d * 72 + r0]           = __float2half_rn(cv[mt][nt][0] + bv.x);
                vt[(d + 1) * 72 + r0]     = __float2half_rn(cv[mt][nt][1] + bv.y);
                vt[d * 72 + r0 + 8]       = __float2half_rn(cv[mt][nt][2] + bv.x);
                vt[(d + 1) * 72 + r0 + 8] = __float2half_rn(cv[mt][nt][3] + bv.y);
            }
    }
    __syncthreads();   // sync #2

    // ---- phase 2: attention (2 warps per head) ----
    {
        const int h = warp >> 1;
        const int mh = warp & 1;
        const int rowbase = mh * 32;

        float s[2][8][4];
#pragma unroll
        for (int a = 0; a < 2; ++a)
#pragma unroll
            for (int t = 0; t < 8; ++t)
#pragma unroll
                for (int r = 0; r < 4; ++r) s[a][t][r] = 0.f;

        // S = Q @ K^T (q pre-scaled)
#pragma unroll
        for (int kt = 0; kt < 2; ++kt) {
            int kc = h * 32 + kt * 16;
            unsigned a0[4], a1[4];
            ldsm4(a0, qh + (rowbase + arow) * 136 + kc + acol);
            ldsm4(a1, qh + (rowbase + 16 + arow) * 136 + kc + acol);
#pragma unroll
            for (int p = 0; p < 4; ++p) {
                unsigned r[4];
                ldsm4(r, kh + (p * 16 + brow) * 136 + kc + bcol);
                mma_16816(s[0][2 * p],     a0, r[0], r[1]);
                mma_16816(s[1][2 * p],     a1, r[0], r[1]);
                mma_16816(s[0][2 * p + 1], a0, r[2], r[3]);
                mma_16816(s[1][2 * p + 1], a1, r[2], r[3]);
            }
        }

        // + (bias+mask) streaming, softmax
        const float* bm = g_bm + ((size_t)((b & 255) * 4 + h)) * 64 * 64;
        float rmax[4] = {-1e30f, -1e30f, -1e30f, -1e30f};
#pragma unroll
        for (int mt = 0; mt < 2; ++mt) {
            int r0 = rowbase + mt * 16 + l4;
#pragma unroll
            for (int nt = 0; nt < 8; ++nt) {
                int col = nt * 8 + lm * 2;
                float2 b0 = __ldcs((const float2*)(bm + r0 * 64 + col));
                float2 b1 = __ldcs((const float2*)(bm + (r0 + 8) * 64 + col));
                s[mt][nt][0] += b0.x;
                s[mt][nt][1] += b0.y;
                s[mt][nt][2] += b1.x;
                s[mt][nt][3] += b1.y;
                rmax[mt * 2]     = fmaxf(rmax[mt * 2],     fmaxf(s[mt][nt][0], s[mt][nt][1]));
                rmax[mt * 2 + 1] = fmaxf(rmax[mt * 2 + 1], fmaxf(s[mt][nt][2], s[mt][nt][3]));
            }
        }
#pragma unroll
        for (int i = 0; i < 4; ++i) {
            rmax[i] = fmaxf(rmax[i], __shfl_xor_sync(0xffffffffu, rmax[i], 1));
            rmax[i] = fmaxf(rmax[i], __shfl_xor_sync(0xffffffffu, rmax[i], 2));
        }
        float rsum[4] = {0.f, 0.f, 0.f, 0.f};
#pragma unroll
        for (int mt = 0; mt < 2; ++mt)
#pragma unroll
            for (int nt = 0; nt < 8; ++nt) {
                s[mt][nt][0] = __expf(s[mt][nt][0] - rmax[mt * 2]);
                s[mt][nt][1] = __expf(s[mt][nt][1] - rmax[mt * 2]);
                s[mt][nt][2] = __expf(s[mt][nt][2] - rmax[mt * 2 + 1]);
                s[mt][nt][3] = __expf(s[mt][nt][3] - rmax[mt * 2 + 1]);
                rsum[mt * 2]     += s[mt][nt][0] + s[mt][nt][1];
                rsum[mt * 2 + 1] += s[mt][nt][2] + s[mt][nt][3];
            }
#pragma unroll
        for (int i = 0; i < 4; ++i) {
            rsum[i] += __shfl_xor_sync(0xffffffffu, rsum[i], 1);
            rsum[i] += __shfl_xor_sync(0xffffffffu, rsum[i], 2);
        }
        float rinv[4];
#pragma unroll
        for (int i = 0; i < 4; ++i) rinv[i] = 1.0f / rsum[i];

        // repack normalized P into A fragments
        unsigned pa[2][4][4];
#pragma unroll
        for (int mt = 0; mt < 2; ++mt)
#pragma unroll
            for (int k2 = 0; k2 < 4; ++k2) {
                pa[mt][k2][0] = h2u(__floats2half2_rn(s[mt][2 * k2][0] * rinv[2 * mt],
                                                      s[mt][2 * k2][1] * rinv[2 * mt]));
                pa[mt][k2][1] = h2u(__floats2half2_rn(s[mt][2 * k2][2] * rinv[2 * mt + 1],
                                                      s[mt][2 * k2][3] * rinv[2 * mt + 1]));
                pa[mt][k2][2] = h2u(__floats2half2_rn(s[mt][2 * k2 + 1][0] * rinv[2 * mt],
                                                      s[mt][2 * k2 + 1][1] * rinv[2 * mt]));
                pa[mt][k2][3] = h2u(__floats2half2_rn(s[mt][2 * k2 + 1][2] * rinv[2 * mt + 1],
                                                      s[mt][2 * k2 + 1][3] * rinv[2 * mt + 1]));
            }

        // O = P @ V
        float o[2][4][4];
#pragma unroll
        for (int a = 0; a < 2; ++a)
#pragma unroll
            for (int t = 0; t < 4; ++t)
#pragma unroll
                for (int r = 0; r < 4; ++r) o[a][t][r] = 0.f;
#pragma unroll
        for (int k2 = 0; k2 < 4; ++k2)
#pragma unroll
            for (int p = 0; p < 2; ++p) {
                unsigned r[4];
                ldsm4(r, vt + (h * 32 + p * 16 + brow) * 72 + k2 * 16 + bcol);
                mma_16816(o[0][2 * p],     pa[0][k2], r[0], r[1]);
                mma_16816(o[1][2 * p],     pa[1][k2], r[0], r[1]);
                mma_16816(o[0][2 * p + 1], pa[0][k2], r[2], r[3]);
                mma_16816(o[1][2 * p + 1], pa[1][k2], r[2], r[3]);
            }
#pragma unroll
        for (int mt = 0; mt < 2; ++mt)
#pragma unroll
            for (int nt = 0; nt < 4; ++nt) {
                int col = h * 32 + nt * 8 + lm * 2;
                int r0 = rowbase + mt * 16 + l4;
                *(__half2*)(oh + r0 * 136 + col) =
                    __floats2half2_rn(o[mt][nt][0], o[mt][nt][1]);
                *(__half2*)(oh + (r0 + 8) * 136 + col) =
                    __floats2half2_rn(o[mt][nt][2], o[mt][nt][3]);
            }
    }
    __syncthreads();   // sync #3

    // ---- phase 3: out = O @ Wproj^T + proj_b (B-frags via LDG) ----
    {
        float c[2][4][4];
#pragma unroll
        for (int a = 0; a < 2; ++a)
#pragma unroll
            for (int t = 0; t < 4; ++t)
#pragma unroll
                for (int r = 0; r < 4; ++r) c[a][t][r] = 0.f;

#pragma unroll
        for (int ktg = 0; ktg < 8; ++ktg) {
            int kc = ktg * 16;
            unsigned a0[4], a1[4];
            ldsm4(a0, oh + (mi * 32 + arow) * 136 + kc + acol);
            ldsm4(a1, oh + (mi * 32 + 16 + arow) * 136 + kc + acol);
#pragma unroll
            for (int nt = 0; nt < 4; ++nt) {
                uint2 f = g_wprojf[(((ni * 4 + nt) * 8 + ktg) << 5) + lane];
                mma_16816(c[0][nt], a0, f.x, f.y);
                mma_16816(c[1][nt], a1, f.x, f.y);
            }
        }

        float* og = out + (size_t)b * NTOK * DIMC;
#pragma unroll
        for (int mt = 0; mt < 2; ++mt)
#pragma unroll
            for (int nt = 0; nt < 4; ++nt) {
                int col = ni * 32 + nt * 8 + lm * 2;
                int r0 = mi * 32 + mt * 16 + l4;
                float2 pb = *(const float2*)(proj_b + col);
                float2 v0 = {c[mt][nt][0] + pb.x, c[mt][nt][1] + pb.y};
                float2 v1 = {c[mt][nt][2] + pb.x, c[mt][nt][3] + pb.y};
                *(float2*)(og + r0 * 128 + col) = v0;
                *(float2*)(og + (r0 + 8) * 128 + col) = v1;
            }
    }
}

// ---------------- launch ----------------
extern "C" void kernel_launch(void* const* d_in, const int* in_sizes, int n_in,
                              void* d_out, int out_size) {
    const float* x       = (const float*)d_in[0];
    const float* mask    = (const float*)d_in[1];
    const float* qkv_w   = (const float*)d_in[2];
    const float* qkv_b   = (const float*)d_in[3];
    const float* proj_w  = (const float*)d_in[4];
    const float* proj_b  = (const float*)d_in[5];
    const float* bias_t  = (const float*)d_in[6];
    const int*   rel_idx = (const int*)d_in[7];
    float* out = (float*)d_out;

    prep_all_k<<<(NWIN * NHEADS * NTOK * NTOK) / 256, 256>>>(mask, bias_t, rel_idx,
                                                             qkv_w, proj_w);

    cudaFuncSetAttribute(swin_attn_kernel,
                         cudaFuncAttributeMaxDynamicSharedMemorySize, SMEM_BYTES);
    swin_attn_kernel<<<NWINDOWS, 256, SMEM_BYTES>>>(x, qkv_b, proj_b, out);
}